// round 2
// baseline (speedup 1.0000x reference)
#include <cuda_runtime.h>
#include <cstdint>

// Problem dims
#define S_LEN 1024
#define B_DIM 256
#define E_DIM 128
#define H_DIM 256
#define O_DIM 2
#define K_DIM (E_DIM + H_DIM)   // 384

// Decomposition: 8 batch groups x 16 hidden groups = 128 CTAs (1 per SM)
#define GB 8
#define GC 16
#define NCTA (GB * GC)
#define BT (B_DIM / GB)          // 32 batch rows per CTA
#define HS (H_DIM / GC)          // 16 hidden units per CTA
#define GT (4 * HS)              // 64 gate columns per CTA
#define NTHR 256

// SMEM strides (padded for bank-conflict-free mma fragment loads)
#define WT_ST 72                 // weight [k][col], 8k+n distinct mod 32
#define ACT_ST 388               // act [m][k], 4r+c distinct mod 32
#define G_ST 72

#define SMEM_F32 (K_DIM*WT_ST + BT*ACT_ST + BT*G_ST + BT*HS + GT + BT + BT)
#define SMEM_BYTES (SMEM_F32 * 4)
static_assert(SMEM_BYTES <= 227 * 1024, "smem too big");

// Global scratch: double-buffered hidden state (tf32-rounded fp32 bits)
__device__ float g_h[2][B_DIM][H_DIM];
__device__ unsigned g_cnt = 0;
__device__ volatile unsigned g_gen = 0;

__device__ __forceinline__ unsigned f2tf(float x) {
    unsigned u; asm("cvt.rna.tf32.f32 %0, %1;" : "=r"(u) : "f"(x)); return u;
}
__device__ __forceinline__ float sigf(float x) { return 1.0f / (1.0f + __expf(-x)); }

__device__ __forceinline__ void mma8(float& d0, float& d1, float& d2, float& d3,
                                     unsigned a0, unsigned a1, unsigned a2, unsigned a3,
                                     unsigned b0, unsigned b1) {
    asm volatile(
        "mma.sync.aligned.m16n8k8.row.col.f32.tf32.tf32.f32 "
        "{%0,%1,%2,%3},{%4,%5,%6,%7},{%8,%9},{%0,%1,%2,%3};"
        : "+f"(d0), "+f"(d1), "+f"(d2), "+f"(d3)
        : "r"(a0), "r"(a1), "r"(a2), "r"(a3), "r"(b0), "r"(b1));
}

// Grid-wide sense-reversing barrier. All 128 CTAs are co-resident (1/SM).
__device__ __forceinline__ void gbar() {
    __syncthreads();
    if (threadIdx.x == 0) {
        __threadfence();                       // publish this CTA's writes
        unsigned gen = g_gen;
        if (atomicAdd(&g_cnt, 1u) == NCTA - 1u) {
            g_cnt = 0;
            __threadfence();
            g_gen = gen + 1u;                  // release
        } else {
            while (g_gen == gen) {}            // volatile spin
            __threadfence();                   // acquire (invalidates L1)
        }
    }
    __syncthreads();
}

__global__ void __launch_bounds__(NTHR, 1)
lstm_kernel(const int* __restrict__ inp, const int* __restrict__ lengths,
            const float* __restrict__ h0, const float* __restrict__ c0,
            const float* __restrict__ emb, const float* __restrict__ w_ih,
            const float* __restrict__ w_hh, const float* __restrict__ b_ih,
            const float* __restrict__ b_hh, const float* __restrict__ dec_w,
            float* __restrict__ out) {
    extern __shared__ float sm[];
    float* sW    = sm;                         // [K_DIM][WT_ST]
    float* sA    = sW + K_DIM * WT_ST;         // [BT][ACT_ST]
    float* sG    = sA + BT * ACT_ST;           // [BT][G_ST]
    float* sC    = sG + BT * G_ST;             // [BT][HS]
    float* sBias = sC + BT * HS;               // [GT]
    int*   sLen  = (int*)(sBias + GT);         // [BT]
    int*   sTok  = sLen + BT;                  // [BT]

    const int tid = threadIdx.x;
    const int cta = blockIdx.x;
    const int gb = cta / GC;
    const int gc = cta % GC;
    const int b0 = gb * BT;

    // ---- one-time init: weights (tf32), bias, lengths, c state, h[0] ----
    for (int idx = tid; idx < K_DIM * GT; idx += NTHR) {
        int k = idx / GT, c = idx % GT;
        int grow = (c / HS) * H_DIM + gc * HS + (c % HS);   // gate order i,f,g,o
        float w = (k < E_DIM) ? w_ih[grow * E_DIM + k] : w_hh[grow * H_DIM + (k - E_DIM)];
        sW[k * WT_ST + c] = __uint_as_float(f2tf(w));
    }
    if (tid < GT) {
        int grow = (tid / HS) * H_DIM + gc * HS + (tid % HS);
        sBias[tid] = b_ih[grow] + b_hh[grow];
    }
    if (tid < BT) sLen[tid] = lengths[b0 + tid];
    for (int idx = tid; idx < BT * HS; idx += NTHR) {
        int m = idx / HS, u = idx % HS;
        sC[idx] = c0[(b0 + m) * H_DIM + gc * HS + u];
    }
    if (gc == 0) {
        for (int idx = tid; idx < BT * H_DIM; idx += NTHR) {
            int m = idx / H_DIM, u = idx % H_DIM;
            g_h[0][b0 + m][u] = __uint_as_float(f2tf(h0[(b0 + m) * H_DIM + u]));
        }
    }
    __syncthreads();
    if (tid == 0) {
        int mx = 0;
        for (int i = 0; i < BT; ++i) mx = max(mx, sLen[i]);
        sTok[0] = mx;
    }
    __syncthreads();
    const int ctaMax = sTok[0];   // rows past their length are dead: skip compute
    gbar();

    const int lane = tid & 31, warp = tid >> 5;
    const int mg = warp >> 2;     // 0..1 : which m16 tile
    const int ng = warp & 3;      // 0..3 : which n16 group

    // ---- recurrence ----
    for (int t = 0; t < S_LEN; ++t) {
        const int cur = t & 1, nxt = cur ^ 1;
        if (t < ctaMax) {
            if (tid < BT) sTok[tid] = inp[t * B_DIM + b0 + tid];
            __syncthreads();

            // act tile: [BT][384] = [emb(x) | h], tf32 bits, float4 stores
            for (int i4 = tid; i4 < BT * 96; i4 += NTHR) {
                int m = i4 / 96, q = i4 % 96;
                float4 v;
                if (q < 32) {
                    const float4* src =
                        reinterpret_cast<const float4*>(emb + (size_t)sTok[m] * E_DIM) + q;
                    v = __ldg(src);
                    v.x = __uint_as_float(f2tf(v.x));
                    v.y = __uint_as_float(f2tf(v.y));
                    v.z = __uint_as_float(f2tf(v.z));
                    v.w = __uint_as_float(f2tf(v.w));
                } else {
                    v = __ldcg(reinterpret_cast<const float4*>(&g_h[cur][b0 + m][0]) + (q - 32));
                }
                *reinterpret_cast<float4*>(&sA[m * ACT_ST + q * 4]) = v;
            }
            __syncthreads();

            // GEMM: gates[32,64] = act[32,384] @ W[384,64] via m16n8k8 tf32
            const float* Ab = &sA[(mg * 16 + (lane >> 2)) * ACT_ST + (lane & 3)];
            const float* Bb = &sW[(lane & 3) * WT_ST + ng * 16 + (lane >> 2)];
            float acc0[4] = {0.f, 0.f, 0.f, 0.f};
            float acc1[4] = {0.f, 0.f, 0.f, 0.f};
            #pragma unroll 8
            for (int kt = 0; kt < 48; ++kt) {
                const float* Ak = Ab + kt * 8;
                unsigned a0 = __float_as_uint(Ak[0]);
                unsigned a1 = __float_as_uint(Ak[8 * ACT_ST]);
                unsigned a2 = __float_as_uint(Ak[4]);
                unsigned a3 = __float_as_uint(Ak[8 * ACT_ST + 4]);
                const float* Bk = Bb + kt * 8 * WT_ST;
                unsigned p0 = __float_as_uint(Bk[0]);
                unsigned p1 = __float_as_uint(Bk[4 * WT_ST]);
                unsigned q0 = __float_as_uint(Bk[8]);
                unsigned q1 = __float_as_uint(Bk[4 * WT_ST + 8]);
                mma8(acc0[0], acc0[1], acc0[2], acc0[3], a0, a1, a2, a3, p0, p1);
                mma8(acc1[0], acc1[1], acc1[2], acc1[3], a0, a1, a2, a3, q0, q1);
            }
            {   // spill gate tile to smem for the elementwise stage
                int r = mg * 16 + (lane >> 2);
                int cb = ng * 16 + 2 * (lane & 3);
                sG[r * G_ST + cb]           = acc0[0];
                sG[r * G_ST + cb + 1]       = acc0[1];
                sG[(r + 8) * G_ST + cb]     = acc0[2];
                sG[(r + 8) * G_ST + cb + 1] = acc0[3];
                sG[r * G_ST + cb + 8]       = acc1[0];
                sG[r * G_ST + cb + 9]       = acc1[1];
                sG[(r + 8) * G_ST + cb + 8] = acc1[2];
                sG[(r + 8) * G_ST + cb + 9] = acc1[3];
            }
            __syncthreads();

            // elementwise LSTM cell update (fp32), snapshot at t == len-1
            #pragma unroll
            for (int rep = 0; rep < (BT * HS + NTHR - 1) / NTHR; ++rep) {
                int idx = tid + rep * NTHR;
                int m = idx / HS, u = idx % HS;
                const float* gm = &sG[m * G_ST];
                float xi = gm[u]          + sBias[u];
                float xf = gm[HS + u]     + sBias[HS + u];
                float xg = gm[2 * HS + u] + sBias[2 * HS + u];
                float xo = gm[3 * HS + u] + sBias[3 * HS + u];
                float ii = sigf(xi), ff = sigf(xf), gg = tanhf(xg), oo = sigf(xo);
                float c = ff * sC[idx] + ii * gg;
                sC[idx] = c;
                float h = oo * tanhf(c);
                int b = b0 + m, ug = gc * HS + u;
                g_h[nxt][b][ug] = __uint_as_float(f2tf(h));
                if (t == sLen[m] - 1) {
                    out[B_DIM * O_DIM + (size_t)b * H_DIM + ug] = h;                      // last_h
                    out[B_DIM * O_DIM + (size_t)B_DIM * H_DIM + (size_t)b * H_DIM + ug] = c; // last_c
                }
            }
        }
        gbar();   // all h[nxt] + snapshots visible before next step
    }

    // ---- decoder: decoded[b][o] = sigmoid(last_h[b] . dec_w[o]) ----
    if (gc == 0) {
        int pair = tid >> 2, part = tid & 3;   // 64 (b,o) pairs x 4-way split-k
        int m = pair >> 1, o = pair & 1;
        int b = b0 + m;
        const float* hrow = out + B_DIM * O_DIM + (size_t)b * H_DIM;
        const float* wrow = dec_w + o * H_DIM;
        float s = 0.f;
        #pragma unroll 16
        for (int u = part * 64; u < part * 64 + 64; ++u)
            s += __ldcg(hrow + u) * wrow[u];
        s += __shfl_xor_sync(0xffffffffu, s, 1);
        s += __shfl_xor_sync(0xffffffffu, s, 2);
        if (part == 0) out[b * O_DIM + o] = 1.0f / (1.0f + __expf(-s));
    }
}

extern "C" void kernel_launch(void* const* d_in, const int* in_sizes, int n_in,
                              void* d_out, int out_size) {
    const int*   inp = (const int*)d_in[0];
    const int*   len = (const int*)d_in[1];
    const float* h0  = (const float*)d_in[2];
    const float* c0  = (const float*)d_in[3];
    const float* emb = (const float*)d_in[4];
    const float* wih = (const float*)d_in[5];
    const float* whh = (const float*)d_in[6];
    const float* bih = (const float*)d_in[7];
    const float* bhh = (const float*)d_in[8];
    const float* dw  = (const float*)d_in[9];
    float* out = (float*)d_out;

    cudaFuncSetAttribute(lstm_kernel, cudaFuncAttributeMaxDynamicSharedMemorySize, SMEM_BYTES);
    lstm_kernel<<<NCTA, NTHR, SMEM_BYTES>>>(inp, len, h0, c0, emb, wih, whh, bih, bhh, dw, out);
}

// round 3
// speedup vs baseline: 1.3525x; 1.3525x over previous
#include <cuda_runtime.h>
#include <cstdint>

// Problem dims
#define S_LEN 1024
#define B_DIM 256
#define E_DIM 128
#define H_DIM 256
#define O_DIM 2
#define K_DIM (E_DIM + H_DIM)   // 384

// Decomposition: 8 batch groups x 16 hidden groups = 128 CTAs (1 per SM)
#define GB 8
#define GC 16
#define NCTA (GB * GC)
#define BT (B_DIM / GB)          // 32 batch rows per CTA
#define HS (H_DIM / GC)          // 16 hidden units per CTA
#define GT (4 * HS)              // 64 gate columns per CTA
#define NTHR 256

// GEMM warp layout: 4 k-split groups x 2 n-halves (fat warps: m32 x n32 each)
#define KS 4
#define KT_TOTAL 48              // 384 / 8
#define KT_PER (KT_TOTAL / KS)   // 12 k-tiles per warp

// SMEM strides (padded for bank-conflict-free mma fragment loads)
#define WT_ST 72                 // weight [k][col]: (8k+c) distinct mod 32
#define ACT_ST 388               // act [m][k]: (4r+k) distinct mod 32
#define G_ST 72

#define SMEM_F32 (K_DIM*WT_ST + BT*ACT_ST + KS*BT*G_ST + BT*HS + GT + BT + BT + 4)
#define SMEM_BYTES (SMEM_F32 * 4)
static_assert(SMEM_BYTES <= 227 * 1024, "smem too big");

// Global scratch: double-buffered hidden state (tf32-rounded fp32 bits)
__device__ float g_h[2][B_DIM][H_DIM];
// Per-group barrier: cnt at [gb][0], gen at [gb][32] (separate 128B lines)
__device__ unsigned g_bar[GB][64];

__device__ __forceinline__ unsigned f2tf(float x) {
    unsigned u; asm("cvt.rna.tf32.f32 %0, %1;" : "=r"(u) : "f"(x)); return u;
}
__device__ __forceinline__ float sigf(float x) { return 1.0f / (1.0f + __expf(-x)); }

__device__ __forceinline__ void mma8(float& d0, float& d1, float& d2, float& d3,
                                     unsigned a0, unsigned a1, unsigned a2, unsigned a3,
                                     unsigned b0, unsigned b1) {
    asm volatile(
        "mma.sync.aligned.m16n8k8.row.col.f32.tf32.tf32.f32 "
        "{%0,%1,%2,%3},{%4,%5,%6,%7},{%8,%9},{%0,%1,%2,%3};"
        : "+f"(d0), "+f"(d1), "+f"(d2), "+f"(d3)
        : "r"(a0), "r"(a1), "r"(a2), "r"(a3), "r"(b0), "r"(b1));
}

// Group-local sense-reversing barrier (16 CTAs), acquire/release semantics.
__device__ __forceinline__ void gbar(int gb) {
    __syncthreads();
    if (threadIdx.x == 0) {
        unsigned* cnt = &g_bar[gb][0];
        unsigned* gen = &g_bar[gb][32];
        unsigned g;
        asm volatile("ld.acquire.gpu.global.u32 %0, [%1];" : "=r"(g) : "l"(gen) : "memory");
        unsigned old;
        asm volatile("atom.acq_rel.gpu.global.add.u32 %0, [%1], %2;"
                     : "=r"(old) : "l"(cnt), "r"(1u) : "memory");
        if (old == GC - 1u) {
            asm volatile("st.relaxed.gpu.global.u32 [%0], %1;" :: "l"(cnt), "r"(0u) : "memory");
            asm volatile("st.release.gpu.global.u32 [%0], %1;" :: "l"(gen), "r"(g + 1u) : "memory");
        } else {
            unsigned v;
            do {
                asm volatile("ld.acquire.gpu.global.u32 %0, [%1];" : "=r"(v) : "l"(gen) : "memory");
            } while (v == g);
        }
    }
    __syncthreads();
}

__global__ void __launch_bounds__(NTHR, 1)
lstm_kernel(const int* __restrict__ inp, const int* __restrict__ lengths,
            const float* __restrict__ h0, const float* __restrict__ c0,
            const float* __restrict__ emb, const float* __restrict__ w_ih,
            const float* __restrict__ w_hh, const float* __restrict__ b_ih,
            const float* __restrict__ b_hh, const float* __restrict__ dec_w,
            float* __restrict__ out) {
    extern __shared__ float sm[];
    float* sW    = sm;                         // [K_DIM][WT_ST]
    float* sA    = sW + K_DIM * WT_ST;         // [BT][ACT_ST]
    float* sG    = sA + BT * ACT_ST;           // [KS][BT][G_ST] gate partials
    float* sC    = sG + KS * BT * G_ST;        // [BT][HS]
    float* sBias = sC + BT * HS;               // [GT]
    int*   sLen  = (int*)(sBias + GT);         // [BT]
    int*   sTok  = sLen + BT;                  // [BT]
    int*   sMax  = sTok + BT;                  // [1]

    const int tid = threadIdx.x;
    const int cta = blockIdx.x;
    const int gb = cta / GC;
    const int gc = cta % GC;
    const int b0 = gb * BT;

    // ---- one-time init: weights (tf32), bias, lengths, c state, h[0] ----
    for (int idx = tid; idx < K_DIM * GT; idx += NTHR) {
        int k = idx / GT, c = idx % GT;
        int grow = (c / HS) * H_DIM + gc * HS + (c % HS);   // gate order i,f,g,o
        float w = (k < E_DIM) ? w_ih[grow * E_DIM + k] : w_hh[grow * H_DIM + (k - E_DIM)];
        sW[k * WT_ST + c] = __uint_as_float(f2tf(w));
    }
    if (tid < GT) {
        int grow = (tid / HS) * H_DIM + gc * HS + (tid % HS);
        sBias[tid] = b_ih[grow] + b_hh[grow];
    }
    if (tid < BT) sLen[tid] = lengths[b0 + tid];
    for (int idx = tid; idx < BT * HS; idx += NTHR) {
        int m = idx / HS, u = idx % HS;
        sC[idx] = c0[(b0 + m) * H_DIM + gc * HS + u];
    }
    if (gc == 0) {
        for (int idx = tid; idx < BT * H_DIM; idx += NTHR) {
            int m = idx / H_DIM, u = idx % H_DIM;
            g_h[0][b0 + m][u] = __uint_as_float(f2tf(h0[(b0 + m) * H_DIM + u]));
        }
    }
    if (tid < BT) sTok[tid] = inp[b0 + tid];   // tokens for t = 0
    __syncthreads();
    if (tid == 0) {
        int mx = 0;
        for (int i = 0; i < BT; ++i) mx = max(mx, sLen[i]);
        sMax[0] = mx;
    }
    __syncthreads();
    const int ctaMax = sMax[0];                // uniform across the group (same rows)

    // prologue: embedding columns of sA for t = 0
    #pragma unroll
    for (int rep = 0; rep < (BT * 32) / NTHR; ++rep) {
        int i4 = tid + rep * NTHR;
        int m = i4 >> 5, q = i4 & 31;
        float4 v = __ldg(reinterpret_cast<const float4*>(emb + (size_t)sTok[m] * E_DIM) + q);
        v.x = __uint_as_float(f2tf(v.x));
        v.y = __uint_as_float(f2tf(v.y));
        v.z = __uint_as_float(f2tf(v.z));
        v.w = __uint_as_float(f2tf(v.w));
        *reinterpret_cast<float4*>(&sA[m * ACT_ST + q * 4]) = v;
    }
    gbar(gb);   // g_h[0] visible group-wide

    const int lane = tid & 31, warp = tid >> 5;
    const int ng = warp & 1;      // n half: 32 cols
    const int ks = warp >> 1;     // k slice: 12 k-tiles

    // ---- recurrence (group-local; early exit at group max length) ----
    for (int t = 0; t < ctaMax; ++t) {
        const int cur = t & 1, nxt = cur ^ 1;

        // phase 1: gather h[t] into sA (cols 128..383) + prefetch next tokens
        if (tid < BT && t + 1 < ctaMax) sTok[tid] = inp[(t + 1) * B_DIM + b0 + tid];
        #pragma unroll
        for (int rep = 0; rep < (BT * 64) / NTHR; ++rep) {
            int i4 = tid + rep * NTHR;
            int m = i4 >> 6, q = i4 & 63;
            float4 v = __ldcg(reinterpret_cast<const float4*>(&g_h[cur][b0 + m][0]) + q);
            *reinterpret_cast<float4*>(&sA[m * ACT_ST + 128 + q * 4]) = v;
        }
        __syncthreads();

        // phase 2: GEMM gates[32,64] += act[32,384] @ W[384,64], k-split x4
        {
            const float* Ab = &sA[(lane >> 2) * ACT_ST + (lane & 3)];
            const float* Bb = &sW[(lane & 3) * WT_ST + ng * 32 + (lane >> 2)];
            float acc[2][4][4] = {};
            #pragma unroll
            for (int kt = 0; kt < KT_PER; ++kt) {
                const int kk = (ks * KT_PER + kt) * 8;
                unsigned a[2][4];
                #pragma unroll
                for (int mg = 0; mg < 2; ++mg) {
                    const float* Ak = Ab + mg * 16 * ACT_ST + kk;
                    a[mg][0] = __float_as_uint(Ak[0]);
                    a[mg][1] = __float_as_uint(Ak[8 * ACT_ST]);
                    a[mg][2] = __float_as_uint(Ak[4]);
                    a[mg][3] = __float_as_uint(Ak[8 * ACT_ST + 4]);
                }
                const float* Bk = Bb + kk * WT_ST;
                #pragma unroll
                for (int j = 0; j < 4; ++j) {
                    unsigned p0 = __float_as_uint(Bk[j * 8]);
                    unsigned p1 = __float_as_uint(Bk[4 * WT_ST + j * 8]);
                    mma8(acc[0][j][0], acc[0][j][1], acc[0][j][2], acc[0][j][3],
                         a[0][0], a[0][1], a[0][2], a[0][3], p0, p1);
                    mma8(acc[1][j][0], acc[1][j][1], acc[1][j][2], acc[1][j][3],
                         a[1][0], a[1][1], a[1][2], a[1][3], p0, p1);
                }
            }
            float* sGp = sG + ks * BT * G_ST;
            #pragma unroll
            for (int mg = 0; mg < 2; ++mg) {
                int r = mg * 16 + (lane >> 2);
                #pragma unroll
                for (int j = 0; j < 4; ++j) {
                    int cb = ng * 32 + j * 8 + 2 * (lane & 3);
                    sGp[r * G_ST + cb]           = acc[mg][j][0];
                    sGp[r * G_ST + cb + 1]       = acc[mg][j][1];
                    sGp[(r + 8) * G_ST + cb]     = acc[mg][j][2];
                    sGp[(r + 8) * G_ST + cb + 1] = acc[mg][j][3];
                }
            }
        }
        __syncthreads();

        // phase 3: elementwise cell update (+ partial-sum combine), then
        //          prefill next step's embedding columns (off critical path)
        #pragma unroll
        for (int rep = 0; rep < (BT * HS) / NTHR; ++rep) {
            int idx = tid + rep * NTHR;
            int m = idx >> 4, u = idx & 15;
            float xi = sBias[u], xf = sBias[HS + u], xg = sBias[2 * HS + u], xo = sBias[3 * HS + u];
            #pragma unroll
            for (int p = 0; p < KS; ++p) {
                const float* gm = &sG[p * BT * G_ST + m * G_ST];
                xi += gm[u];
                xf += gm[HS + u];
                xg += gm[2 * HS + u];
                xo += gm[3 * HS + u];
            }
            float ii = sigf(xi), ff = sigf(xf), gg = tanhf(xg), oo = sigf(xo);
            float c = ff * sC[idx] + ii * gg;
            sC[idx] = c;
            float h = oo * tanhf(c);
            int b = b0 + m, ug = gc * HS + u;
            g_h[nxt][b][ug] = __uint_as_float(f2tf(h));
            if (t == sLen[m] - 1) {
                out[B_DIM * O_DIM + (size_t)b * H_DIM + ug] = h;                          // last_h
                out[B_DIM * O_DIM + (size_t)B_DIM * H_DIM + (size_t)b * H_DIM + ug] = c;  // last_c
            }
        }
        if (t + 1 < ctaMax) {
            #pragma unroll
            for (int rep = 0; rep < (BT * 32) / NTHR; ++rep) {
                int i4 = tid + rep * NTHR;
                int m = i4 >> 5, q = i4 & 31;
                float4 v = __ldg(reinterpret_cast<const float4*>(emb + (size_t)sTok[m] * E_DIM) + q);
                v.x = __uint_as_float(f2tf(v.x));
                v.y = __uint_as_float(f2tf(v.y));
                v.z = __uint_as_float(f2tf(v.z));
                v.w = __uint_as_float(f2tf(v.w));
                *reinterpret_cast<float4*>(&sA[m * ACT_ST + q * 4]) = v;
            }
        }
        gbar(gb);   // h[nxt] + snapshots visible group-wide
    }

    // ---- decoder: decoded[b][o] = sigmoid(last_h[b] . dec_w[o]) ----
    if (gc == 0) {
        int pair = tid >> 2, part = tid & 3;   // 64 (b,o) pairs x 4-way split-k
        int m = pair >> 1, o = pair & 1;
        int b = b0 + m;
        const float* hrow = out + B_DIM * O_DIM + (size_t)b * H_DIM;
        const float* wrow = dec_w + o * H_DIM;
        float s = 0.f;
        #pragma unroll 16
        for (int u = part * 64; u < part * 64 + 64; ++u)
            s += __ldcg(hrow + u) * wrow[u];
        s += __shfl_xor_sync(0xffffffffu, s, 1);
        s += __shfl_xor_sync(0xffffffffu, s, 2);
        if (part == 0) out[b * O_DIM + o] = 1.0f / (1.0f + __expf(-s));
    }
}

extern "C" void kernel_launch(void* const* d_in, const int* in_sizes, int n_in,
                              void* d_out, int out_size) {
    const int*   inp = (const int*)d_in[0];
    const int*   len = (const int*)d_in[1];
    const float* h0  = (const float*)d_in[2];
    const float* c0  = (const float*)d_in[3];
    const float* emb = (const float*)d_in[4];
    const float* wih = (const float*)d_in[5];
    const float* whh = (const float*)d_in[6];
    const float* bih = (const float*)d_in[7];
    const float* bhh = (const float*)d_in[8];
    const float* dw  = (const float*)d_in[9];
    float* out = (float*)d_out;

    cudaFuncSetAttribute(lstm_kernel, cudaFuncAttributeMaxDynamicSharedMemorySize, SMEM_BYTES);
    lstm_kernel<<<NCTA, NTHR, SMEM_BYTES>>>(inp, len, h0, c0, emb, wih, whh, bih, bhh, dw, out);
}

// round 4
// speedup vs baseline: 1.5058x; 1.1134x over previous
#include <cuda_runtime.h>
#include <cstdint>

// Problem dims
#define S_LEN 1024
#define B_DIM 256
#define E_DIM 128
#define H_DIM 256
#define O_DIM 2
#define K_DIM (E_DIM + H_DIM)   // 384

// Decomposition: 8 batch groups x 16 hidden groups = 128 CTAs (1 per SM)
#define GB 8
#define GC 16
#define NCTA (GB * GC)
#define BT (B_DIM / GB)          // 32 batch rows per CTA
#define HS (H_DIM / GC)          // 16 hidden units per CTA
#define GT (4 * HS)              // 64 gate columns per CTA
#define NTHR 256

// GEMM warp layout: 4 k-split groups x 2 n-halves (fat warps: m32 x n32 each)
// Per warp: 4 x-part k-tiles (k<128) + 8 h-part k-tiles (k>=128) = 12 total
#define KS 4
#define NXT 4                    // x-part k-tiles per warp
#define NHT 8                    // h-part k-tiles per warp
#define NKT (NXT + NHT)          // 12

// SMEM strides (padded for bank-conflict-free mma fragment loads)
#define WT_ST 72                 // weight [k][col]: (8k+c) distinct mod 32
#define ACT_ST 388               // act [m][k]: (4r+k) distinct mod 32
#define G_ST 72

#define SMEM_F32 (K_DIM*WT_ST + BT*ACT_ST + KS*BT*G_ST + BT*HS + GT + BT + BT + 4)
#define SMEM_BYTES (SMEM_F32 * 4)
static_assert(SMEM_BYTES <= 227 * 1024, "smem too big");

// Global scratch: double-buffered hidden state (tf32-rounded fp32 bits)
__device__ float g_h[2][B_DIM][H_DIM];
// Per-group barrier: cnt at [gb][0], gen at [gb][32] (separate 128B lines)
__device__ unsigned g_bar[GB][64];

__device__ __forceinline__ unsigned f2tf(float x) {
    unsigned u; asm("cvt.rna.tf32.f32 %0, %1;" : "=r"(u) : "f"(x)); return u;
}
__device__ __forceinline__ float sigf(float x) {
    return __fdividef(1.0f, 1.0f + __expf(-x));
}
__device__ __forceinline__ float tanhfast(float x) {
    // 2*sigmoid(2x) - 1, MUFU-based; rel err ~1e-6
    return 2.0f * __fdividef(1.0f, 1.0f + __expf(-2.0f * x)) - 1.0f;
}

__device__ __forceinline__ void mma8(float& d0, float& d1, float& d2, float& d3,
                                     unsigned a0, unsigned a1, unsigned a2, unsigned a3,
                                     unsigned b0, unsigned b1) {
    asm volatile(
        "mma.sync.aligned.m16n8k8.row.col.f32.tf32.tf32.f32 "
        "{%0,%1,%2,%3},{%4,%5,%6,%7},{%8,%9},{%0,%1,%2,%3};"
        : "+f"(d0), "+f"(d1), "+f"(d2), "+f"(d3)
        : "r"(a0), "r"(a1), "r"(a2), "r"(a3), "r"(b0), "r"(b1));
}

#define CP_ASYNC16(dst_u32, src) \
    asm volatile("cp.async.cg.shared.global [%0], [%1], 16;" :: "r"(dst_u32), "l"(src))
#define CP_COMMIT() asm volatile("cp.async.commit_group;")
#define CP_WAIT0()  asm volatile("cp.async.wait_group 0;")

// Group-local sense-reversing barrier (16 CTAs), acquire/release semantics.
__device__ __forceinline__ void gbar(int gb) {
    __syncthreads();
    if (threadIdx.x == 0) {
        unsigned* cnt = &g_bar[gb][0];
        unsigned* gen = &g_bar[gb][32];
        unsigned g;
        asm volatile("ld.acquire.gpu.global.u32 %0, [%1];" : "=r"(g) : "l"(gen) : "memory");
        unsigned old;
        asm volatile("atom.acq_rel.gpu.global.add.u32 %0, [%1], %2;"
                     : "=r"(old) : "l"(cnt), "r"(1u) : "memory");
        if (old == GC - 1u) {
            asm volatile("st.relaxed.gpu.global.u32 [%0], %1;" :: "l"(cnt), "r"(0u) : "memory");
            asm volatile("st.release.gpu.global.u32 [%0], %1;" :: "l"(gen), "r"(g + 1u) : "memory");
        } else {
            unsigned v;
            do {
                asm volatile("ld.acquire.gpu.global.u32 %0, [%1];" : "=r"(v) : "l"(gen) : "memory");
            } while (v == g);
        }
    }
    __syncthreads();
}

__global__ void __launch_bounds__(NTHR, 1)
lstm_kernel(const int* __restrict__ inp, const int* __restrict__ lengths,
            const float* __restrict__ h0, const float* __restrict__ c0,
            const float* __restrict__ emb, const float* __restrict__ w_ih,
            const float* __restrict__ w_hh, const float* __restrict__ b_ih,
            const float* __restrict__ b_hh, const float* __restrict__ dec_w,
            float* __restrict__ out) {
    extern __shared__ float sm[];
    float* sW    = sm;                         // [K_DIM][WT_ST]
    float* sA    = sW + K_DIM * WT_ST;         // [BT][ACT_ST]
    float* sG    = sA + BT * ACT_ST;           // [KS][BT][G_ST] gate partials
    float* sC    = sG + KS * BT * G_ST;        // [BT][HS]
    float* sBias = sC + BT * HS;               // [GT]
    int*   sLen  = (int*)(sBias + GT);         // [BT]
    int*   sTok  = sLen + BT;                  // [BT]
    int*   sMax  = sTok + BT;                  // [1]

    const int tid = threadIdx.x;
    const int cta = blockIdx.x;
    const int gb = cta / GC;
    const int gc = cta % GC;
    const int b0 = gb * BT;

    // ---- one-time init: weights (tf32), bias, lengths, c state, h[0] ----
    for (int idx = tid; idx < K_DIM * GT; idx += NTHR) {
        int k = idx / GT, c = idx % GT;
        int grow = (c / HS) * H_DIM + gc * HS + (c % HS);   // gate order i,f,g,o
        float w = (k < E_DIM) ? w_ih[grow * E_DIM + k] : w_hh[grow * H_DIM + (k - E_DIM)];
        sW[k * WT_ST + c] = __uint_as_float(f2tf(w));
    }
    if (tid < GT) {
        int grow = (tid / HS) * H_DIM + gc * HS + (tid % HS);
        sBias[tid] = b_ih[grow] + b_hh[grow];
    }
    if (tid < BT) sLen[tid] = lengths[b0 + tid];
    for (int idx = tid; idx < BT * HS; idx += NTHR) {
        int m = idx / HS, u = idx % HS;
        sC[idx] = c0[(b0 + m) * H_DIM + gc * HS + u];
    }
    if (gc == 0) {
        for (int idx = tid; idx < BT * H_DIM; idx += NTHR) {
            int m = idx / H_DIM, u = idx % H_DIM;
            g_h[0][b0 + m][u] = __uint_as_float(f2tf(h0[(b0 + m) * H_DIM + u]));
        }
    }
    if (tid < BT) sTok[tid] = inp[b0 + tid];   // tokens for t = 0
    __syncthreads();
    if (tid == 0) {
        int mx = 0;
        for (int i = 0; i < BT; ++i) mx = max(mx, sLen[i]);
        sMax[0] = mx;
    }
    __syncthreads();
    const int ctaMax = sMax[0];                // uniform across the group (same rows)

    const int lane = tid & 31, warp = tid >> 5;
    const int ng = warp & 1;      // n half: 32 cols
    const int ks = warp >> 1;     // k slice

    // ---- preload this warp's B fragments into registers (step-invariant) ----
    unsigned bw[NKT][4][2];
    #pragma unroll
    for (int i = 0; i < NKT; ++i) {
        int ktg = (i < NXT) ? (ks * NXT + i) : (16 + ks * NHT + (i - NXT));
        const float* Bk = &sW[(ktg * 8 + (lane & 3)) * WT_ST + ng * 32 + (lane >> 2)];
        #pragma unroll
        for (int j = 0; j < 4; ++j) {
            bw[i][j][0] = __float_as_uint(Bk[j * 8]);
            bw[i][j][1] = __float_as_uint(Bk[4 * WT_ST + j * 8]);
        }
    }

    // prologue: embedding columns of sA for t = 0
    #pragma unroll
    for (int rep = 0; rep < (BT * 32) / NTHR; ++rep) {
        int i4 = tid + rep * NTHR;
        int m = i4 >> 5, q = i4 & 31;
        float4 v = __ldg(reinterpret_cast<const float4*>(emb + (size_t)sTok[m] * E_DIM) + q);
        v.x = __uint_as_float(f2tf(v.x));
        v.y = __uint_as_float(f2tf(v.y));
        v.z = __uint_as_float(f2tf(v.z));
        v.w = __uint_as_float(f2tf(v.w));
        *reinterpret_cast<float4*>(&sA[m * ACT_ST + q * 4]) = v;
    }
    gbar(gb);   // g_h[0] visible group-wide

    // ---- recurrence (group-local; early exit at group max length) ----
    for (int t = 0; t < ctaMax; ++t) {
        const int cur = t & 1, nxt = cur ^ 1;

        // phase 1a: issue async h[t] gather into sA cols 128..383 (no reg landing)
        #pragma unroll
        for (int rep = 0; rep < (BT * 64) / NTHR; ++rep) {
            int i4 = tid + rep * NTHR;
            int m = i4 >> 6, q = i4 & 63;
            unsigned dst = (unsigned)__cvta_generic_to_shared(&sA[m * ACT_ST + 128 + q * 4]);
            CP_ASYNC16(dst, &g_h[cur][b0 + m][q * 4]);
        }
        CP_COMMIT();
        // prefetch next tokens (independent)
        if (tid < BT && t + 1 < ctaMax) sTok[tid] = inp[(t + 1) * B_DIM + b0 + tid];

        // phase 1b: x-part GEMM (emb columns prefetched last step) while gather flies
        float acc[2][4][4] = {};
        const float* Ab = &sA[(lane >> 2) * ACT_ST + (lane & 3)];
        #pragma unroll
        for (int i = 0; i < NXT; ++i) {
            const int kk = (ks * NXT + i) * 8;
            unsigned a[2][4];
            #pragma unroll
            for (int mg = 0; mg < 2; ++mg) {
                const float* Ak = Ab + mg * 16 * ACT_ST + kk;
                a[mg][0] = __float_as_uint(Ak[0]);
                a[mg][1] = __float_as_uint(Ak[8 * ACT_ST]);
                a[mg][2] = __float_as_uint(Ak[4]);
                a[mg][3] = __float_as_uint(Ak[8 * ACT_ST + 4]);
            }
            #pragma unroll
            for (int j = 0; j < 4; ++j) {
                mma8(acc[0][j][0], acc[0][j][1], acc[0][j][2], acc[0][j][3],
                     a[0][0], a[0][1], a[0][2], a[0][3], bw[i][j][0], bw[i][j][1]);
                mma8(acc[1][j][0], acc[1][j][1], acc[1][j][2], acc[1][j][3],
                     a[1][0], a[1][1], a[1][2], a[1][3], bw[i][j][0], bw[i][j][1]);
            }
        }
        CP_WAIT0();
        __syncthreads();

        // phase 2: h-part GEMM (k = 128..383)
        #pragma unroll
        for (int i = 0; i < NHT; ++i) {
            const int kk = (16 + ks * NHT + i) * 8;
            unsigned a[2][4];
            #pragma unroll
            for (int mg = 0; mg < 2; ++mg) {
                const float* Ak = Ab + mg * 16 * ACT_ST + kk;
                a[mg][0] = __float_as_uint(Ak[0]);
                a[mg][1] = __float_as_uint(Ak[8 * ACT_ST]);
                a[mg][2] = __float_as_uint(Ak[4]);
                a[mg][3] = __float_as_uint(Ak[8 * ACT_ST + 4]);
            }
            #pragma unroll
            for (int j = 0; j < 4; ++j) {
                mma8(acc[0][j][0], acc[0][j][1], acc[0][j][2], acc[0][j][3],
                     a[0][0], a[0][1], a[0][2], a[0][3], bw[NXT + i][j][0], bw[NXT + i][j][1]);
                mma8(acc[1][j][0], acc[1][j][1], acc[1][j][2], acc[1][j][3],
                     a[1][0], a[1][1], a[1][2], a[1][3], bw[NXT + i][j][0], bw[NXT + i][j][1]);
            }
        }
        {   // spill gate partial tile to smem
            float* sGp = sG + ks * BT * G_ST;
            #pragma unroll
            for (int mg = 0; mg < 2; ++mg) {
                int r = mg * 16 + (lane >> 2);
                #pragma unroll
                for (int j = 0; j < 4; ++j) {
                    int cb = ng * 32 + j * 8 + 2 * (lane & 3);
                    sGp[r * G_ST + cb]           = acc[mg][j][0];
                    sGp[r * G_ST + cb + 1]       = acc[mg][j][1];
                    sGp[(r + 8) * G_ST + cb]     = acc[mg][j][2];
                    sGp[(r + 8) * G_ST + cb + 1] = acc[mg][j][3];
                }
            }
        }
        __syncthreads();

        // phase 3: elementwise cell update (+ partial-sum combine), then
        //          prefill next step's embedding columns (off critical path)
        #pragma unroll
        for (int rep = 0; rep < (BT * HS) / NTHR; ++rep) {
            int idx = tid + rep * NTHR;
            int m = idx >> 4, u = idx & 15;
            float xi = sBias[u], xf = sBias[HS + u], xg = sBias[2 * HS + u], xo = sBias[3 * HS + u];
            #pragma unroll
            for (int p = 0; p < KS; ++p) {
                const float* gm = &sG[p * BT * G_ST + m * G_ST];
                xi += gm[u];
                xf += gm[HS + u];
                xg += gm[2 * HS + u];
                xo += gm[3 * HS + u];
            }
            float ii = sigf(xi), ff = sigf(xf), gg = tanhfast(xg), oo = sigf(xo);
            float c = ff * sC[idx] + ii * gg;
            sC[idx] = c;
            float h = oo * tanhfast(c);
            int b = b0 + m, ug = gc * HS + u;
            g_h[nxt][b][ug] = __uint_as_float(f2tf(h));
            if (t == sLen[m] - 1) {
                out[B_DIM * O_DIM + (size_t)b * H_DIM + ug] = h;                          // last_h
                out[B_DIM * O_DIM + (size_t)B_DIM * H_DIM + (size_t)b * H_DIM + ug] = c;  // last_c
            }
        }
        if (t + 1 < ctaMax) {
            #pragma unroll
            for (int rep = 0; rep < (BT * 32) / NTHR; ++rep) {
                int i4 = tid + rep * NTHR;
                int m = i4 >> 5, q = i4 & 31;
                float4 v = __ldg(reinterpret_cast<const float4*>(emb + (size_t)sTok[m] * E_DIM) + q);
                v.x = __uint_as_float(f2tf(v.x));
                v.y = __uint_as_float(f2tf(v.y));
                v.z = __uint_as_float(f2tf(v.z));
                v.w = __uint_as_float(f2tf(v.w));
                *reinterpret_cast<float4*>(&sA[m * ACT_ST + q * 4]) = v;
            }
        }
        gbar(gb);   // h[nxt] + snapshots visible group-wide
    }

    // ---- decoder: decoded[b][o] = sigmoid(last_h[b] . dec_w[o]) ----
    if (gc == 0) {
        int pair = tid >> 2, part = tid & 3;   // 64 (b,o) pairs x 4-way split-k
        int m = pair >> 1, o = pair & 1;
        int b = b0 + m;
        const float* hrow = out + B_DIM * O_DIM + (size_t)b * H_DIM;
        const float* wrow = dec_w + o * H_DIM;
        float s = 0.f;
        #pragma unroll 16
        for (int u = part * 64; u < part * 64 + 64; ++u)
            s += __ldcg(hrow + u) * wrow[u];
        s += __shfl_xor_sync(0xffffffffu, s, 1);
        s += __shfl_xor_sync(0xffffffffu, s, 2);
        if (part == 0) out[b * O_DIM + o] = 1.0f / (1.0f + __expf(-s));
    }
}

extern "C" void kernel_launch(void* const* d_in, const int* in_sizes, int n_in,
                              void* d_out, int out_size) {
    const int*   inp = (const int*)d_in[0];
    const int*   len = (const int*)d_in[1];
    const float* h0  = (const float*)d_in[2];
    const float* c0  = (const float*)d_in[3];
    const float* emb = (const float*)d_in[4];
    const float* wih = (const float*)d_in[5];
    const float* whh = (const float*)d_in[6];
    const float* bih = (const float*)d_in[7];
    const float* bhh = (const float*)d_in[8];
    const float* dw  = (const float*)d_in[9];
    float* out = (float*)d_out;

    cudaFuncSetAttribute(lstm_kernel, cudaFuncAttributeMaxDynamicSharedMemorySize, SMEM_BYTES);
    lstm_kernel<<<NCTA, NTHR, SMEM_BYTES>>>(inp, len, h0, c0, emb, wih, whh, bih, bhh, dw, out);
}